// round 5
// baseline (speedup 1.0000x reference)
#include <cuda_runtime.h>
#include <cstdint>

// Problem constants (fixed by the reference)
#define HH 1024
#define WW 1024
#define HWSZ (HH * WW)      // 1,048,576 cells
#define NF 64               // features
#define NP 100000           // pillars

// Per-cell winner, encoded as (pillar_index + 1); 0 == empty.
// BSS zero-init makes the very first call correct; clear_winner_kernel
// (launched after gather) restores the all-empty state for the next replay.
__device__ __align__(16) int g_winner[HWSZ];

// coords is int32 on device (JAX x64-off materializes int64 as int32).
// Layout [NP, 3]: x = col 2, y = col 1. Last-writer-wins == max pillar idx.
// 4 pillars per thread: 12 ints = 3 aligned int4 loads -> high MLP,
// 4 spread ATOMG per thread.
__global__ __launch_bounds__(256) void scatter_winner_kernel(
        const int4* __restrict__ coords4) {
    int t = blockIdx.x * blockDim.x + threadIdx.x;
    if (t >= NP / 4) return;
    int4 a = __ldg(&coords4[3 * t + 0]);
    int4 b = __ldg(&coords4[3 * t + 1]);
    int4 c = __ldg(&coords4[3 * t + 2]);
    int p0 = 4 * t;

    int ys[4] = {a.y, b.x, b.w, c.z};
    int xs[4] = {a.z, b.y, c.x, c.w};
    #pragma unroll
    for (int j = 0; j < 4; j++) {
        int x = xs[j], y = ys[j];
        if (x >= 0 && x < WW && y >= 0 && y < HH) {
            atomicMax(&g_winner[y * WW + x], p0 + j + 1);
        }
    }
}

// One thread per (4-cell group, 4-feature chunk) tile.
// blockIdx.y = feature chunk (0..15); blockIdx.x covers cell groups.
// Winner array is re-read by all 16 chunk slices -> L2 hits (4MB resident).
// Output stores use evict-first (.cs) so the 256MB stream doesn't evict the
// L2-resident feature matrix.
__global__ __launch_bounds__(256) void gather_out_kernel(
        const float* __restrict__ feat,
        float* __restrict__ out) {
    int g = blockIdx.x * blockDim.x + threadIdx.x;   // cell-group id
    int f4 = blockIdx.y;                              // feature chunk
    int c0 = g * 4;

    int4 w4 = __ldg(reinterpret_cast<const int4*>(&g_winner[c0]));
    int w[4] = {w4.x, w4.y, w4.z, w4.w};

    float4 v[4];
    #pragma unroll
    for (int j = 0; j < 4; j++) {
        if (w[j] > 0) {
            v[j] = __ldg(reinterpret_cast<const float4*>(
                feat + (size_t)(w[j] - 1) * NF + f4 * 4));
        } else {
            v[j] = make_float4(0.f, 0.f, 0.f, 0.f);
        }
    }
    #pragma unroll
    for (int k = 0; k < 4; k++) {
        float4 o;
        o.x = reinterpret_cast<const float*>(&v[0])[k];
        o.y = reinterpret_cast<const float*>(&v[1])[k];
        o.z = reinterpret_cast<const float*>(&v[2])[k];
        o.w = reinterpret_cast<const float*>(&v[3])[k];
        __stcs(reinterpret_cast<float4*>(out + (size_t)(f4 * 4 + k) * HWSZ + c0), o);
    }
}

// Restore the all-empty winner state for the next graph replay.
__global__ __launch_bounds__(512) void clear_winner_kernel() {
    int i = blockIdx.x * blockDim.x + threadIdx.x;
    if (i < HWSZ / 4) {
        reinterpret_cast<int4*>(g_winner)[i] = make_int4(0, 0, 0, 0);
    }
}

extern "C" void kernel_launch(void* const* d_in, const int* in_sizes, int n_in,
                              void* d_out, int out_size) {
    const float* pillar_features = (const float*)d_in[0]; // [NP, 64] f32
    const int*   coords          = (const int*)d_in[1];   // [NP, 3] i32
    float*       out             = (float*)d_out;         // [1,64,1024,1024] f32

    {
        int threads = 256;
        int work = NP / 4;
        int blocks = (work + threads - 1) / threads;
        scatter_winner_kernel<<<blocks, threads>>>(
            reinterpret_cast<const int4*>(coords));
    }
    {
        int threads = 256;
        dim3 grid((HWSZ / 4 + threads - 1) / threads, NF / 4);
        gather_out_kernel<<<grid, threads>>>(pillar_features, out);
    }
    {
        int threads = 512;
        int blocks = (HWSZ / 4 + threads - 1) / threads;
        clear_winner_kernel<<<blocks, threads>>>();
    }
}